// round 9
// baseline (speedup 1.0000x reference)
#include <cuda_runtime.h>

#define IN_F   4096
#define OUT_F  4096
#define RANK   8
#define MAX_TOKENS 8192

// Intermediate t[tok][r] = x @ core1^T  (256 KB, lives in L2)
__device__ float g_t[MAX_TOKENS * RANK];

// ---------------------------------------------------------------------------
// Stage 1: t[tok, r] = sum_i x[tok, i] * core1[r, i]
// 256 threads = 8 warps; each warp owns 2 tokens across the FULL row
// (32 lane-iterations). ~48 regs -> 4 blocks/SM (50% occ). Per iteration a
// warp issues 10 independent LDG.128 (2 x-stream + 8 c1/L1) before the FFMA
// block, unroll 4 for deep MLP. c1 L2 traffic = 512 blocks x 128KB = 67 MB.
// Launched as 3 token-range slices purely so ncu's skip-5 profiles stage1.
// ---------------------------------------------------------------------------
__global__ void __launch_bounds__(256) tt_stage1(const float* __restrict__ x,
                                                 const float* __restrict__ c1,
                                                 int tokbase) {
    const int warp = threadIdx.x >> 5;
    const int lane = threadIdx.x & 31;
    const int token0 = tokbase + blockIdx.x * 16 + warp * 2;

    const float4* xp = reinterpret_cast<const float4*>(x)
                     + (size_t)token0 * (IN_F / 4);
    const float4* cp = reinterpret_cast<const float4*>(c1);

    float acc[2][RANK];
#pragma unroll
    for (int t = 0; t < 2; t++)
#pragma unroll
        for (int r = 0; r < RANK; r++) acc[t][r] = 0.0f;

    // 1024 float4 per token row, 32 lanes -> 32 iterations
#pragma unroll 4
    for (int i = lane; i < IN_F / 4; i += 32) {
        const float4 x0 = __ldcs(xp + i);                     // stream x
        const float4 x1 = __ldcs(xp + (IN_F / 4) + i);
#pragma unroll
        for (int r = 0; r < RANK; r++) {
            const float4 c = __ldg(cp + (size_t)r * (IN_F / 4) + i);
            acc[0][r] += x0.x * c.x + x0.y * c.y + x0.z * c.z + x0.w * c.w;
            acc[1][r] += x1.x * c.x + x1.y * c.y + x1.z * c.z + x1.w * c.w;
        }
    }

#pragma unroll
    for (int t = 0; t < 2; t++)
#pragma unroll
        for (int r = 0; r < RANK; r++) {
            float v = acc[t][r];
#pragma unroll
            for (int off = 16; off; off >>= 1)
                v += __shfl_xor_sync(0xffffffffu, v, off);
            if (lane == 0)
                g_t[(size_t)(token0 + t) * RANK + r] = v;
        }
}

// ---------------------------------------------------------------------------
// Stage 2: y[tok, o] = bias[o] + sum_r t[tok, r] * core0[o, r]
// 256 threads, 64 tokens x 1024 outputs per block. t is read as TWO LDS.128
// per token (float4 pairs) instead of 8 scalar LDS.32 -> 4x fewer shared
// loads and a shorter per-token dependency ladder. c0 coeffs live in regs,
// stores are STG.128 evict-first.
// ---------------------------------------------------------------------------
__global__ void __launch_bounds__(256) tt_stage2(const float* __restrict__ c0,
                                                 const float* __restrict__ bias,
                                                 float* __restrict__ y) {
    __shared__ float4 ts[64 * 2];                 // t[64][8] as float4 pairs
    const int tid = threadIdx.x;
    const int token0 = blockIdx.y * 64;
    const int o = blockIdx.x * 1024 + tid * 4;

    {   // fill ts: 128 float4 = 512 floats
        const float4* tg = reinterpret_cast<const float4*>(g_t + (size_t)token0 * RANK);
        if (tid < 128) ts[tid] = tg[tid];
    }

    float4 ca[4], cb[4];
#pragma unroll
    for (int j = 0; j < 4; j++) {
        const float4* c = reinterpret_cast<const float4*>(c0 + (size_t)(o + j) * RANK);
        ca[j] = __ldg(c);
        cb[j] = __ldg(c + 1);
    }
    const float4 bv = __ldg(reinterpret_cast<const float4*>(bias + o));

    __syncthreads();

#pragma unroll 4
    for (int tok = 0; tok < 64; tok++) {
        const float4 tA = ts[tok * 2];            // t[0..3]  (LDS.128 bcast)
        const float4 tB = ts[tok * 2 + 1];        // t[4..7]

        float4 res;
        res.x = bv.x + ca[0].x * tA.x + ca[0].y * tA.y + ca[0].z * tA.z + ca[0].w * tA.w
                     + cb[0].x * tB.x + cb[0].y * tB.y + cb[0].z * tB.z + cb[0].w * tB.w;
        res.y = bv.y + ca[1].x * tA.x + ca[1].y * tA.y + ca[1].z * tA.z + ca[1].w * tA.w
                     + cb[1].x * tB.x + cb[1].y * tB.y + cb[1].z * tB.z + cb[1].w * tB.w;
        res.z = bv.z + ca[2].x * tA.x + ca[2].y * tA.y + ca[2].z * tA.z + ca[2].w * tA.w
                     + cb[2].x * tB.x + cb[2].y * tB.y + cb[2].z * tB.z + cb[2].w * tB.w;
        res.w = bv.w + ca[3].x * tA.x + ca[3].y * tA.y + ca[3].z * tA.z + ca[3].w * tA.w
                     + cb[3].x * tB.x + cb[3].y * tB.y + cb[3].z * tB.z + cb[3].w * tB.w;

        __stcs(reinterpret_cast<float4*>(y + (size_t)(token0 + tok) * OUT_F + o),
               res);
    }
}

extern "C" void kernel_launch(void* const* d_in, const int* in_sizes, int n_in,
                              void* d_out, int out_size) {
    const float* x    = (const float*)d_in[0];   // [TOKENS, IN_F]
    const float* c0   = (const float*)d_in[1];   // [OUT_F, RANK]
    const float* c1   = (const float*)d_in[2];   // [RANK, IN_F]
    const float* bias = (const float*)d_in[3];   // [OUT_F]
    float* y = (float*)d_out;

    const int tokens = in_sizes[0] / IN_F;       // 8192
    const int nblk   = tokens / 16;              // 512 stage1 blocks total

    // Stage 1 in 3 slices (so ncu's skip-5 lands on a stage1 launch).
    const int b0 = nblk / 3;                     // 170
    const int b1 = nblk / 3;                     // 170
    const int b2 = nblk - b0 - b1;               // 172
    tt_stage1<<<b0, 256>>>(x, c1, 0);
    tt_stage1<<<b1, 256>>>(x, c1, b0 * 16);
    tt_stage1<<<b2, 256>>>(x, c1, (b0 + b1) * 16);

    // Stage 2: 4 output chunks x 64-token groups = 512 blocks
    dim3 g2(OUT_F / 1024, tokens / 64);
    tt_stage2<<<g2, 256>>>(c0, bias, y);
}

// round 11
// speedup vs baseline: 1.3221x; 1.3221x over previous
#include <cuda_runtime.h>

#define IN_F   4096
#define OUT_F  4096
#define RANK   8
#define MAX_TOKENS 8192
#define NPART 8                   // 4 IN_F quarters x 2 sub-halves

// Partial t per (quarter, sub-half); stage2 sums the 8 partials.
__device__ float g_part[NPART][MAX_TOKENS * RANK];   // 8 x 256 KB

// ---------------------------------------------------------------------------
// Stage 1 (quarter): t_p[tok, r] = sum_{i in segment} x[tok,i] * c1[r,i]
// Block = 256 thr / 8 warps / 16 tokens / one IN_F quarter (1024 floats).
// The block's c1 quarter tile (8 ranks x 256 float4 = 32 KB) is staged into
// STATIC SMEM once, so inner-loop c1 reads are LDS.128 (no L1tex queue use).
// Only x's 4 LDG.128/iter remain in L1tex -> MLP_p1 ~ 8, below the
// cross-CTA contention knee (B300 spread model).
// Warp w: tokens (w>>1)*4, sub-half (w&1); EACH (q,sub) writes ITS OWN
// g_part slot (round-10 bug was both subs clobbering one slot).
// ---------------------------------------------------------------------------
__global__ void __launch_bounds__(256) tt_stage1(const float* __restrict__ x,
                                                 const float* __restrict__ c1) {
    __shared__ float4 c1s[RANK * 256];            // 32 KB quarter tile

    const int tid  = threadIdx.x;
    const int q    = blockIdx.y;                  // which IN_F quarter
    const int warp = tid >> 5;
    const int lane = tid & 31;

    // Stage the c1 quarter: 2048 float4, 8 per thread, coalesced.
    const float4* c1g = reinterpret_cast<const float4*>(c1);
#pragma unroll
    for (int j = tid; j < RANK * 256; j += 256) {
        const int r = j >> 8;
        const int i = j & 255;
        c1s[j] = c1g[(size_t)r * (IN_F / 4) + q * 256 + i];
    }
    __syncthreads();

    const int token0 = blockIdx.x * 16 + (warp >> 1) * 4;
    const int sub    = warp & 1;                  // 128-float4 sub-segment

    const float4* xp = reinterpret_cast<const float4*>(x)
                     + (size_t)token0 * (IN_F / 4) + q * 256 + sub * 128;
    const float4* cs = c1s + sub * 128;

    float acc[4][RANK];
#pragma unroll
    for (int t = 0; t < 4; t++)
#pragma unroll
        for (int r = 0; r < RANK; r++) acc[t][r] = 0.0f;

    // 128 float4 per warp segment, 32 lanes -> 4 iterations
#pragma unroll
    for (int i = lane; i < 128; i += 32) {
        float4 xv[4];
#pragma unroll
        for (int t = 0; t < 4; t++)
            xv[t] = __ldcs(xp + (size_t)t * (IN_F / 4) + i);   // stream x
#pragma unroll
        for (int r = 0; r < RANK; r++) {
            const float4 c = cs[r * 256 + i];                  // LDS.128
#pragma unroll
            for (int t = 0; t < 4; t++) {
                acc[t][r] += xv[t].x * c.x + xv[t].y * c.y
                           + xv[t].z * c.z + xv[t].w * c.w;
            }
        }
    }

    const int slot = q * 2 + sub;                 // own partial slot
#pragma unroll
    for (int t = 0; t < 4; t++)
#pragma unroll
        for (int r = 0; r < RANK; r++) {
            float v = acc[t][r];
#pragma unroll
            for (int off = 16; off; off >>= 1)
                v += __shfl_xor_sync(0xffffffffu, v, off);
            if (lane == 0)
                g_part[slot][(size_t)(token0 + t) * RANK + r] = v;
        }
}

// ---------------------------------------------------------------------------
// Stage 2: y[tok, o] = bias[o] + sum_r t[tok, r] * core0[o, r]
// Round-9 stage2 (best: 25.6us); smem t-tile = fixed-order sum of the 8
// partials (128 threads x 8 float4 from L2 -> negligible).
// ---------------------------------------------------------------------------
__global__ void __launch_bounds__(256) tt_stage2(const float* __restrict__ c0,
                                                 const float* __restrict__ bias,
                                                 float* __restrict__ y) {
    __shared__ float4 ts[64 * 2];                 // t[64][8] as float4 pairs
    const int tid = threadIdx.x;
    const int token0 = blockIdx.y * 64;
    const int o = blockIdx.x * 1024 + tid * 4;

    if (tid < 128) {
        const size_t base = (size_t)token0 * RANK / 4;   // in float4 units
        float4 s = make_float4(0.f, 0.f, 0.f, 0.f);
#pragma unroll
        for (int p = 0; p < NPART; p++) {
            const float4 v = reinterpret_cast<const float4*>(g_part[p])[base + tid];
            s.x += v.x; s.y += v.y; s.z += v.z; s.w += v.w;
        }
        ts[tid] = s;
    }

    float4 ca[4], cb[4];
#pragma unroll
    for (int j = 0; j < 4; j++) {
        const float4* c = reinterpret_cast<const float4*>(c0 + (size_t)(o + j) * RANK);
        ca[j] = __ldg(c);
        cb[j] = __ldg(c + 1);
    }
    const float4 bv = __ldg(reinterpret_cast<const float4*>(bias + o));

    __syncthreads();

#pragma unroll 4
    for (int tok = 0; tok < 64; tok++) {
        const float4 tA = ts[tok * 2];
        const float4 tB = ts[tok * 2 + 1];

        float4 res;
        res.x = bv.x + ca[0].x * tA.x + ca[0].y * tA.y + ca[0].z * tA.z + ca[0].w * tA.w
                     + cb[0].x * tB.x + cb[0].y * tB.y + cb[0].z * tB.z + cb[0].w * tB.w;
        res.y = bv.y + ca[1].x * tA.x + ca[1].y * tA.y + ca[1].z * tA.z + ca[1].w * tA.w
                     + cb[1].x * tB.x + cb[1].y * tB.y + cb[1].z * tB.z + cb[1].w * tB.w;
        res.z = bv.z + ca[2].x * tA.x + ca[2].y * tA.y + ca[2].z * tA.z + ca[2].w * tA.w
                     + cb[2].x * tB.x + cb[2].y * tB.y + cb[2].z * tB.z + cb[2].w * tB.w;
        res.w = bv.w + ca[3].x * tA.x + ca[3].y * tA.y + ca[3].z * tA.z + ca[3].w * tA.w
                     + cb[3].x * tB.x + cb[3].y * tB.y + cb[3].z * tB.z + cb[3].w * tB.w;

        __stcs(reinterpret_cast<float4*>(y + (size_t)(token0 + tok) * OUT_F + o),
               res);
    }
}

// Empty pad kernels: make launches/replay = 5 so ncu's "-s 5 -c 1" lands on
// a stage1 launch. Removed once stage1 is profiled.
__global__ void tt_nop() {}

extern "C" void kernel_launch(void* const* d_in, const int* in_sizes, int n_in,
                              void* d_out, int out_size) {
    const float* x    = (const float*)d_in[0];   // [TOKENS, IN_F]
    const float* c0   = (const float*)d_in[1];   // [OUT_F, RANK]
    const float* c1   = (const float*)d_in[2];   // [RANK, IN_F]
    const float* bias = (const float*)d_in[3];   // [OUT_F]
    float* y = (float*)d_out;

    const int tokens = in_sizes[0] / IN_F;       // 8192

    // Stage 1: (token groups of 16) x (4 IN_F quarters) = 512 x 4 blocks
    dim3 g1(tokens / 16, NPART / 2);
    tt_stage1<<<g1, 256>>>(x, c1);

    // Stage 2: 4 output chunks x 64-token groups = 512 blocks
    dim3 g2(OUT_F / 1024, tokens / 64);
    tt_stage2<<<g2, 256>>>(c0, bias, y);

    // Profiling pads (launch count -> 5 per replay)
    tt_nop<<<1, 32>>>();
    tt_nop<<<1, 32>>>();
    tt_nop<<<1, 32>>>();
}

// round 12
// speedup vs baseline: 1.3928x; 1.0535x over previous
#include <cuda_runtime.h>

#define IN_F   4096
#define OUT_F  4096
#define RANK   8
#define MAX_TOKENS 8192

// Intermediate t[tok][r] = x @ core1^T  (256 KB, lives in L2)
__device__ float g_t[MAX_TOKENS * RANK];

// ---------------------------------------------------------------------------
// Stage 1: t[tok, r] = sum_i x[tok, i] * core1[r, i]
// EXACT round-6 structure (known 41us): 128 threads = 4 warps covering the
// same 4 tokens; warp w reduces i-quarter [w*1024,(w+1)*1024).
// SINGLE CHANGE vs round 6: x loads use DEFAULT policy (no __ldcs).
// __ldcs has been on every x load in every 41us variant; this is the A/B.
// ---------------------------------------------------------------------------
__global__ void __launch_bounds__(128) tt_stage1(const float* __restrict__ x,
                                                 const float* __restrict__ c1) {
    __shared__ float part[4][4][RANK];            // [warp][tok][r]

    const int warp = threadIdx.x >> 5;
    const int lane = threadIdx.x & 31;
    const int token0 = blockIdx.x * 4;

    const float4* xp = reinterpret_cast<const float4*>(x)
                     + (size_t)token0 * (IN_F / 4) + warp * 256;
    const float4* cp = reinterpret_cast<const float4*>(c1) + warp * 256;

    float acc[4][RANK];
#pragma unroll
    for (int t = 0; t < 4; t++)
#pragma unroll
        for (int r = 0; r < RANK; r++) acc[t][r] = 0.0f;

    // 256 float4 per warp-quarter, 32 lanes -> 8 iterations
#pragma unroll 2
    for (int i = lane; i < 256; i += 32) {
        float4 xv[4];
#pragma unroll
        for (int t = 0; t < 4; t++)
            xv[t] = xp[(size_t)t * (IN_F / 4) + i];        // DEFAULT load
#pragma unroll
        for (int r = 0; r < RANK; r++) {
            const float4 c = __ldg(cp + (size_t)r * (IN_F / 4) + i);
#pragma unroll
            for (int t = 0; t < 4; t++) {
                acc[t][r] += xv[t].x * c.x + xv[t].y * c.y
                           + xv[t].z * c.z + xv[t].w * c.w;
            }
        }
    }

#pragma unroll
    for (int t = 0; t < 4; t++)
#pragma unroll
        for (int r = 0; r < RANK; r++) {
            float v = acc[t][r];
#pragma unroll
            for (int off = 16; off; off >>= 1)
                v += __shfl_xor_sync(0xffffffffu, v, off);
            if (lane == 0) part[warp][t][r] = v;
        }
    __syncthreads();

    if (threadIdx.x < 4 * RANK) {
        const int t = threadIdx.x >> 3;
        const int r = threadIdx.x & 7;
        g_t[(size_t)(token0 + t) * RANK + r] =
            part[0][t][r] + part[1][t][r] + part[2][t][r] + part[3][t][r];
    }
}

// ---------------------------------------------------------------------------
// Stage 2: y[tok, o] = bias[o] + sum_r t[tok, r] * core0[o, r]
// Round-9 version (best measured: 25.6us): 64 tokens x 1024 outputs per
// block, t via LDS.128 float4 pairs, c0 coeffs in regs, STG.128 stores.
// ---------------------------------------------------------------------------
__global__ void __launch_bounds__(256) tt_stage2(const float* __restrict__ c0,
                                                 const float* __restrict__ bias,
                                                 float* __restrict__ y) {
    __shared__ float4 ts[64 * 2];                 // t[64][8] as float4 pairs
    const int tid = threadIdx.x;
    const int token0 = blockIdx.y * 64;
    const int o = blockIdx.x * 1024 + tid * 4;

    if (tid < 128) {
        const float4* tg = reinterpret_cast<const float4*>(g_t + (size_t)token0 * RANK);
        ts[tid] = tg[tid];
    }

    float4 ca[4], cb[4];
#pragma unroll
    for (int j = 0; j < 4; j++) {
        const float4* c = reinterpret_cast<const float4*>(c0 + (size_t)(o + j) * RANK);
        ca[j] = __ldg(c);
        cb[j] = __ldg(c + 1);
    }
    const float4 bv = __ldg(reinterpret_cast<const float4*>(bias + o));

    __syncthreads();

#pragma unroll 4
    for (int tok = 0; tok < 64; tok++) {
        const float4 tA = ts[tok * 2];
        const float4 tB = ts[tok * 2 + 1];

        float4 res;
        res.x = bv.x + ca[0].x * tA.x + ca[0].y * tA.y + ca[0].z * tA.z + ca[0].w * tA.w
                     + cb[0].x * tB.x + cb[0].y * tB.y + cb[0].z * tB.z + cb[0].w * tB.w;
        res.y = bv.y + ca[1].x * tA.x + ca[1].y * tA.y + ca[1].z * tA.z + ca[1].w * tA.w
                     + cb[1].x * tB.x + cb[1].y * tB.y + cb[1].z * tB.z + cb[1].w * tB.w;
        res.z = bv.z + ca[2].x * tA.x + ca[2].y * tA.y + ca[2].z * tA.z + ca[2].w * tA.w
                     + cb[2].x * tB.x + cb[2].y * tB.y + cb[2].z * tB.z + cb[2].w * tB.w;
        res.w = bv.w + ca[3].x * tA.x + ca[3].y * tA.y + ca[3].z * tA.z + ca[3].w * tA.w
                     + cb[3].x * tB.x + cb[3].y * tB.y + cb[3].z * tB.z + cb[3].w * tB.w;

        __stcs(reinterpret_cast<float4*>(y + (size_t)(token0 + tok) * OUT_F + o),
               res);
    }
}

extern "C" void kernel_launch(void* const* d_in, const int* in_sizes, int n_in,
                              void* d_out, int out_size) {
    const float* x    = (const float*)d_in[0];   // [TOKENS, IN_F]
    const float* c0   = (const float*)d_in[1];   // [OUT_F, RANK]
    const float* c1   = (const float*)d_in[2];   // [RANK, IN_F]
    const float* bias = (const float*)d_in[3];   // [OUT_F]
    float* y = (float*)d_out;

    const int tokens = in_sizes[0] / IN_F;       // 8192

    // Stage 1: 4 tokens/block, 4 warps share them (quarter-row each)
    tt_stage1<<<tokens / 4, 128>>>(x, c1);

    // Stage 2: 4 output chunks x 64-token groups = 512 blocks
    dim3 g2(OUT_F / 1024, tokens / 64);
    tt_stage2<<<g2, 256>>>(c0, bias, y);
}